// round 6
// baseline (speedup 1.0000x reference)
#include <cuda_runtime.h>

// Problem constants (fixed by the reference)
#define B_     4
#define N_     4096
#define E_     128
#define CACHE_ 32
#define NK_    4
#define CE_    32      // channels per unit (E / NK)
#define M_     128     // N / CACHE
#define BNE_   (B_*N_*E_)
#define NW_    2       // warps per unit
#define CPW_   16      // channels per warp
#define KP_    8       // packed channel pairs per warp

// Inter-layer scratch (device globals: no allocation in kernel_launch)
__device__ float g_x [BNE_];
__device__ float g_xa[BNE_];

typedef unsigned long long u64;

__device__ __forceinline__ float tanh_fast(float x) {
    float y;
    asm("tanh.approx.f32 %0, %1;" : "=f"(y) : "f"(x));
    return y;
}
__device__ __forceinline__ u64 pk(float lo, float hi) {
    u64 r; asm("mov.b64 %0, {%1, %2};" : "=l"(r) : "f"(lo), "f"(hi)); return r;
}
__device__ __forceinline__ void upk(u64 x, float& lo, float& hi) {
    asm("mov.b64 {%0, %1}, %2;" : "=f"(lo), "=f"(hi) : "l"(x));
}
__device__ __forceinline__ u64 fma2(u64 a, u64 b, u64 c) {
    u64 d; asm("fma.rn.f32x2 %0, %1, %2, %3;" : "=l"(d) : "l"(a), "l"(b), "l"(c)); return d;
}
__device__ __forceinline__ u64 mul2(u64 a, u64 b) {
    u64 d; asm("mul.rn.f32x2 %0, %1, %2;" : "=l"(d) : "l"(a), "l"(b)); return d;
}
__device__ __forceinline__ u64 add2(u64 a, u64 b) {
    u64 d; asm("add.rn.f32x2 %0, %1, %2;" : "=l"(d) : "l"(a), "l"(b)); return d;
}

// 2 warps per (b,g,n) unit. lane = row-in-group. Warp w owns channels
// [w*16, w*16+16) as 8 packed f32 pairs. Rescaled: u2=(xi/2)/0.9^j, v2=(xa/2)/0.9^j.
// Weights channel-packed in smem: sWc[c] = (Wi[c], Wj[c]) so per-step dots
// accumulate directly into packed (SF,DF) — no scalar reduce on the chain.
// Partial running dots per warp (linear split): X2w=(Ax_w,Bx_w), A2w=(Aa_w,Ba_w).
// X' = .9X + .09A + .01S with P2 = .9X+.09A precomputed off-chain, so the
// post-dot publish path is 1 fma2 + 1 STS.64. One __syncthreads per step.
__global__ void __launch_bounds__(64, 14)
ncn_layer(const float* __restrict__ X, const float* __restrict__ XA,
          const float* __restrict__ W,         // 256 floats: Wi[4][32], Wj[4][32]
          float* __restrict__ YX, float* __restrict__ YA,
          int s)                                // group-index stride (0 or 1)
{
    __shared__ float tile[CACHE_][CACHE_ + 1];
    __shared__ u64 ebuf[2][NW_][CACHE_];        // [parity][warp][lane] = (Ax_w,Bx_w)
    __shared__ __align__(16) u64 sWc[CE_];      // (Wi[c], Wj[c]) per channel

    const int t    = threadIdx.x;
    const int w    = t >> 5;                    // warp in block (0/1)
    const int lane = t & 31;                    // row-in-group
    const int blk  = blockIdx.x;                // 0 .. 2047
    const int n    = blk & (NK_ - 1);
    const int g    = (blk >> 2) & (M_ - 1);
    const int b    = blk >> 9;

    if (t < CE_)
        sWc[t] = pk(W[n * CE_ + t], W[E_ + n * CE_ + t]);

    const long long bBase    = (long long)b * N_ * E_;
    const long long chanBase = (long long)n * CE_ + lane;
    const int cw = w * CPW_;                    // this warp's first channel

    u64 u2[KP_], v2[KP_];

    // ---- gather xi tile: warp w loads rows [w*16, w*16+16), coalesced ----
    #pragma unroll
    for (int r = 0; r < CPW_; ++r) {
        int rr  = cw + r;
        int row = ((g + rr * s) & (M_ - 1)) * CACHE_ + rr;
        tile[rr][lane] = X[bBase + (long long)row * E_ + chanBase];
    }
    __syncthreads();
    #pragma unroll
    for (int k = 0; k < KP_; ++k)
        u2[k] = pk(0.5f * tile[lane][cw + 2 * k], 0.5f * tile[lane][cw + 2 * k + 1]);
    __syncthreads();

    // ---- gather xa tile ----
    #pragma unroll
    for (int r = 0; r < CPW_; ++r) {
        int rr  = cw + r;
        int row = ((g + rr * s) & (M_ - 1)) * CACHE_ + rr;
        tile[rr][lane] = XA[bBase + (long long)row * E_ + chanBase];
    }
    __syncthreads();
    #pragma unroll
    for (int k = 0; k < KP_; ++k)
        v2[k] = pk(0.5f * tile[lane][cw + 2 * k], 0.5f * tile[lane][cw + 2 * k + 1]);

    const u64 K09  = pk(0.9f,  0.9f);
    const u64 K01  = pk(0.1f,  0.1f);
    const u64 K009 = pk(0.09f, 0.09f);
    const u64 K001 = pk(0.01f, 0.01f);
    const u64 K2   = pk(2.f, 2.f);
    const u64 Z    = pk(0.f, 0.f);
    const ulonglong2* sWc2 = reinterpret_cast<const ulonglong2*>(sWc);

    // ---- initial partials: X2w=(Ax_w,Bx_w), A2w=(Aa_w,Ba_w), packed ----
    u64 X2w = Z, A2w = Z;
    #pragma unroll
    for (int k = 0; k < KP_; ++k) {
        ulonglong2 ww = sWc2[(cw >> 1) + k];    // (Wi,Wj) for ch c0, c1
        float x0, x1, a0, a1;
        upk(u2[k], x0, x1);
        upk(v2[k], a0, a1);
        X2w = fma2(pk(x0, x0), ww.x, X2w);
        X2w = fma2(pk(x1, x1), ww.y, X2w);
        A2w = fma2(pk(a0, a0), ww.x, A2w);
        A2w = fma2(pk(a1, a1), ww.y, A2w);
    }
    X2w = mul2(X2w, K2);                        // undo half-scale
    A2w = mul2(A2w, K2);
    u64 P2 = fma2(X2w, K09, mul2(A2w, K009));   // .9X + .09A (for step 0)
    ebuf[0][w][lane] = X2w;                     // publish for step 0
    __syncthreads();

    float sc = 1.0f;                  // 0.9^j
    float cj = 0.05f / 0.9f;          // 0.05 / 0.9^(j+1)

    // ---- 32-step recurrence ----
    #pragma unroll 1
    for (int j = 0; j < CACHE_; ++j) {
        const int p = j & 1;

        // sim = (Ax_own + Ax_other)[lane] + (Bx_w0 + Bx_w1)[j]
        u64 oth = ebuf[p][1 - w][lane];
        u64 bj0 = ebuf[p][0][j];                // broadcast LDS
        u64 bj1 = ebuf[p][1][j];
        float Axw, Bxw, oAx, oBx, j0x, j0y, j1x, j1y;
        upk(X2w, Axw, Bxw);
        upk(oth, oAx, oBx);
        upk(bj0, j0x, j0y);
        upk(bj1, j1x, j1y);
        float sim = (Axw + oAx) + (j0y + j1y);

        u64 sim2 = pk(sim, sim);
        u64 s2   = pk(sc, sc);
        u64 c2   = pk(cj, cj);
        u64 aA = Z, aB = Z, aC = Z, aD = Z;     // packed (SF,DF) partials
        #pragma unroll
        for (int k = 0; k < KP_; ++k) {
            u64 uj = __shfl_sync(0xffffffffu, u2[k], j);    // pre-update row j
            u64 T  = mul2(s2, fma2(sim2, uj, u2[k]));       // true-scale T
            float t0, t1; upk(T, t0, t1);
            float f0 = tanh_fast(t0), f1 = tanh_fast(t1);
            u64 F = pk(f0, f1);
            ulonglong2 ww = sWc2[(cw >> 1) + k];
            if (k & 1) { aB = fma2(pk(f0, f0), ww.x, aB); aD = fma2(pk(f1, f1), ww.y, aD); }
            else       { aA = fma2(pk(f0, f0), ww.x, aA); aC = fma2(pk(f1, f1), ww.y, aC); }
            v2[k] = fma2(c2,  F,     v2[k]);                // ~xa update
            u2[k] = fma2(K01, v2[k], u2[k]);                // ~xi update
        }
        u64 S2 = add2(add2(aA, aB), add2(aC, aD));          // packed (SF,DF)

        X2w = fma2(S2, K001, P2);                           // X' = .9X+.09A+.01S
        ebuf[p ^ 1][w][lane] = X2w;                         // publish (STS.64)
        A2w = fma2(A2w, K09, mul2(S2, K01));                // off-chain
        P2  = fma2(X2w, K09, mul2(A2w, K009));              // for next step
        __syncthreads();                                    // one bar per step

        sc *= 0.9f;
        cj *= (1.0f / 0.9f);
    }

    const float fscale = 2.0f * sc;   // undo half-scale and 0.9^32 rescale

    // ---- scatter yi ----
    #pragma unroll
    for (int k = 0; k < KP_; ++k) {
        float l, h; upk(u2[k], l, h);
        tile[lane][cw + 2 * k]     = fscale * l;
        tile[lane][cw + 2 * k + 1] = fscale * h;
    }
    __syncthreads();
    #pragma unroll
    for (int r = 0; r < CPW_; ++r) {
        int rr  = cw + r;
        int row = ((g + rr * s) & (M_ - 1)) * CACHE_ + rr;
        YX[bBase + (long long)row * E_ + chanBase] = tile[rr][lane];
    }
    __syncthreads();

    // ---- scatter ya ----
    #pragma unroll
    for (int k = 0; k < KP_; ++k) {
        float l, h; upk(v2[k], l, h);
        tile[lane][cw + 2 * k]     = fscale * l;
        tile[lane][cw + 2 * k + 1] = fscale * h;
    }
    __syncthreads();
    #pragma unroll
    for (int r = 0; r < CPW_; ++r) {
        int rr  = cw + r;
        int row = ((g + rr * s) & (M_ - 1)) * CACHE_ + rr;
        YA[bBase + (long long)row * E_ + chanBase] = tile[rr][lane];
    }
}

extern "C" void kernel_launch(void* const* d_in, const int* in_sizes, int n_in,
                              void* d_out, int out_size) {
    const float* x  = (const float*)d_in[0];
    const float* xa = (const float*)d_in[1];
    const float* W  = (const float*)d_in[2];
    float* out = (float*)d_out;

    float *gx = nullptr, *gxa = nullptr;
    cudaGetSymbolAddress((void**)&gx,  g_x);
    cudaGetSymbolAddress((void**)&gxa, g_xa);

    dim3 grid(B_ * M_ * NK_);   // 2048 blocks
    dim3 block(64);             // 2 warps per unit

    // Layer 0: stage shift s = 0 (contiguous groups)
    ncn_layer<<<grid, block>>>(x, xa, W, gx, gxa, 0);
    // Layer 1: stage shift s = 1 (block = (g + o) % m), writes final output
    ncn_layer<<<grid, block>>>(gx, gxa, W + 2 * E_, out, out + BNE_, 1);
}